// round 4
// baseline (speedup 1.0000x reference)
#include <cuda_runtime.h>

// PRNN_1769526526374: J2 plane-strain plasticity RNN.
// R4: deviatoric reformulation (tr(ep)==0 exactly -> p = K*(e0+e1), state is
// ts = -2mu*ep), W2 weights demoted to smem via non-hoistable LDS.64 (-18
// regs), step loop unrolled x2 for cross-step ILP, launch_bounds(128,5) to
// hold 5 blocks/SM.

namespace {
constexpr int Bb  = 4096;
constexpr int Ss  = 512;
constexpr int TPB = 128;
constexpr int T   = 8;              // steps per reduction chunk
constexpr int ROW = 3 * TPB + 2;    // in F2 units

typedef unsigned long long F2;

__device__ __forceinline__ F2 pk2(float lo, float hi) {
    F2 r; asm("mov.b64 %0, {%1, %2};" : "=l"(r) : "f"(lo), "f"(hi)); return r;
}
__device__ __forceinline__ void upk2(F2 v, float& lo, float& hi) {
    asm("mov.b64 {%0, %1}, %2;" : "=f"(lo), "=f"(hi) : "l"(v));
}
__device__ __forceinline__ F2 mul2(F2 a, F2 b) {
    F2 r; asm("mul.rn.f32x2 %0, %1, %2;" : "=l"(r) : "l"(a), "l"(b)); return r;
}
__device__ __forceinline__ F2 add2(F2 a, F2 b) {
    F2 r; asm("add.rn.f32x2 %0, %1, %2;" : "=l"(r) : "l"(a), "l"(b)); return r;
}
__device__ __forceinline__ F2 fma2(F2 a, F2 b, F2 c) {
    F2 r; asm("fma.rn.f32x2 %0, %1, %2, %3;" : "=l"(r) : "l"(a), "l"(b), "l"(c)); return r;
}
// Non-hoistable shared load (keeps W2 out of the register file).
__device__ __forceinline__ F2 lds2(unsigned addr) {
    F2 r; asm volatile("ld.shared.b64 %0, [%1];" : "=l"(r) : "r"(addr)); return r;
}
} // namespace

__global__ void __launch_bounds__(TPB, 5) prnn_kernel(
    const float* __restrict__ x,    // [B,S,3]
    const float* __restrict__ W1,   // [384,3]
    const float* __restrict__ W2,   // [3,384]
    float* __restrict__ out)        // [B,S,3]
{
    const float MUv      = (float)(3130.0 / (2.0 * 1.3));
    const float TWO_MU   = 2.0f * MUv;
    const float THREE_MU = 3.0f * MUv;
    const float LAM      = (float)(3130.0 * 0.3 / (1.3 * 0.4));
    const float Kb       = LAM + (2.0f / 3.0f) * MUv;   // bulk-ish: p = Kb*tr
    const float Ah = 64.8f, Bh = 33.6f;
    const float INV_C = (float)(1.0 / 0.003407);
    const float BC    = (float)(33.6 / 0.003407);

    const F2 MU2   = pk2(MUv, MUv);
    const F2 TMU2  = pk2(TWO_MU, TWO_MU);
    const F2 NTT2  = pk2(-TWO_MU / 3.0f, -TWO_MU / 3.0f);  // -(2mu/3)
    const F2 K2    = pk2(Kb, Kb);
    const F2 C15   = pk2(1.5f, 1.5f);
    const F2 C3    = pk2(3.0f, 3.0f);

    __shared__ F2 sx2[Ss * 3];        // 12 KB
    __shared__ F2 part[T * ROW];      // 24.1 KB
    __shared__ F2 sw2[TPB * 9];       // 9 KB, packed W2 per point

    const int tid = threadIdx.x;
    const int t3  = 3 * tid;
    const int b0  = 2 * blockIdx.x;

    const float* xb0 = x + (long)b0 * (Ss * 3);
    const float* xb1 = xb0 + Ss * 3;
    for (int i = tid; i < Ss * 3; i += TPB) sx2[i] = pk2(xb0[i], xb1[i]);

    // W1 in registers (head of the chain), W2 in smem (tail of the chain).
    F2 w1p[9];
#pragma unroll
    for (int i = 0; i < 9; ++i) { float w = W1[tid * 9 + i]; w1p[i] = pk2(w, w); }
#pragma unroll
    for (int o = 0; o < 3; ++o)
#pragma unroll
        for (int j = 0; j < 3; ++j) {
            float w = W2[o * 384 + t3 + j];
            sw2[tid * 9 + o * 3 + j] = pk2(w, w);
        }
    const unsigned w2a = (unsigned)__cvta_generic_to_shared(sw2 + tid * 9);

    // State: ts_i = -2mu*ep_i (packed), kappa + cached (B*exp(-k/C) - A).
    F2 ts0 = 0, ts1 = 0, ts2 = 0, ts3 = 0;
    float kapA = 0.f, kapB = 0.f;
    float bexmA = Bh - Ah, bexmB = Bh - Ah;

    float* outb0 = out + (long)b0 * (Ss * 3);
    float* outb1 = outb0 + Ss * 3;

    __syncthreads();

    for (int s0i = 0; s0i < Ss; s0i += T) {
#pragma unroll 2
        for (int si = 0; si < T; ++si) {
            const int s = s0i + si;
            const F2 x0 = sx2[3 * s + 0];
            const F2 x1 = sx2[3 * s + 1];
            const F2 x2 = sx2[3 * s + 2];

            // fc1
            const F2 e0 = fma2(w1p[0], x0, fma2(w1p[1], x1, mul2(w1p[2], x2)));
            const F2 e1 = fma2(w1p[3], x0, fma2(w1p[4], x1, mul2(w1p[5], x2)));
            const F2 g2 = fma2(w1p[6], x0, fma2(w1p[7], x1, mul2(w1p[8], x2)));

            // deviatoric trial stress: s_i = 2mu*dev(e)_i + ts_i
            const F2 tr  = add2(e0, e1);            // tr(ee) == tr(e) exactly
            const F2 ptr = mul2(NTT2, tr);          // -(2mu/3)*tr
            F2 s0d = fma2(TMU2, e0, add2(ts0, ptr));
            F2 s1d = fma2(TMU2, e1, add2(ts1, ptr));
            F2 s2d = add2(ts2, ptr);
            F2 s3d = fma2(MU2, g2, ts3);            // mu*gxy - 2mu*ep3
            const F2 p2 = mul2(K2, tr);             // pressure

            F2 acc = mul2(s0d, s0d);
            acc = fma2(s1d, s1d, acc);
            acc = fma2(s2d, s2d, acc);
            const F2 qsq2 = fma2(C15, acc, mul2(C3, mul2(s3d, s3d)));

            float qsA, qsB;
            upk2(qsq2, qsA, qsB);
            const float rqA = rsqrtf(fmaxf(qsA, 1e-24f));
            const float rqB = rsqrtf(fmaxf(qsB, 1e-24f));
            const float qA  = fmaxf(qsA, 1e-24f) * rqA;
            const float qB  = fmaxf(qsB, 1e-24f) * rqB;

            const float fA = qA + bexmA;   // q - (A - B*exp(-kap/C))
            const float fB = qB + bexmB;

            if (__any_sync(0xffffffffu, (fA > 0.f) | (fB > 0.f))) {
                // Seed = exact first Newton step from dg=0 via cached bex,
                // then 2 fixed iterations (quadratically past f32 precision).
                float dgA = __fdividef(fmaxf(fA, 0.f),
                                       THREE_MU + (bexmA + Ah) * INV_C);
                float dgB = __fdividef(fmaxf(fB, 0.f),
                                       THREE_MU + (bexmB + Ah) * INV_C);
#pragma unroll
                for (int it = 0; it < 2; ++it) {
                    const float ekA = __expf(-(kapA + dgA) * INV_C);
                    const float ekB = __expf(-(kapB + dgB) * INV_C);
                    const float rA  = qA - THREE_MU * dgA - Ah + Bh * ekA;
                    const float rB  = qB - THREE_MU * dgB - Ah + Bh * ekB;
                    dgA = fmaxf(dgA + __fdividef(rA, THREE_MU + BC * ekA), 0.f);
                    dgB = fmaxf(dgB + __fdividef(rB, THREE_MU + BC * ekB), 0.f);
                }
                kapA += dgA;
                kapB += dgB;
                bexmA = Bh * __expf(-kapA * INV_C) - Ah;
                bexmB = Bh * __expf(-kapB * INV_C) - Ah;

                // radial return: one coefficient serves stress AND state.
                const F2 NN2 = pk2(-THREE_MU * dgA * rqA, -THREE_MU * dgB * rqB);
                ts0 = fma2(NN2, s0d, ts0);
                ts1 = fma2(NN2, s1d, ts1);
                ts2 = fma2(NN2, s2d, ts2);
                ts3 = fma2(NN2, s3d, ts3);
                s0d = fma2(NN2, s0d, s0d);
                s1d = fma2(NN2, s1d, s1d);
                s3d = fma2(NN2, s3d, s3d);
            }

            // physical stresses for output
            const F2 sig0 = add2(s0d, p2);
            const F2 sig1 = add2(s1d, p2);

            // projection with smem-resident W2 (LDS.64, not hoistable)
            const F2 q0 = lds2(w2a +  0), q1 = lds2(w2a +  8), q2 = lds2(w2a + 16);
            const F2 q3 = lds2(w2a + 24), q4 = lds2(w2a + 32), q5 = lds2(w2a + 40);
            const F2 q6 = lds2(w2a + 48), q7 = lds2(w2a + 56), q8 = lds2(w2a + 64);
            F2* pr = part + si * ROW + t3;
            pr[0] = fma2(q0, sig0, fma2(q1, sig1, mul2(q2, s3d)));
            pr[1] = fma2(q3, sig0, fma2(q4, sig1, mul2(q5, s3d)));
            pr[2] = fma2(q6, sig0, fma2(q7, sig1, mul2(q8, s3d)));
        }
        __syncthreads();

        // 24 threads: each sums 128 packed partials for one (step, output).
        if (tid < 3 * T) {
            const int si = tid / 3;
            const int o  = tid - 3 * si;
            const F2* pr = part + si * ROW + o;
            F2 a0 = 0, a1 = 0, a2 = 0, a3 = 0;
#pragma unroll 8
            for (int m = 0; m < TPB; m += 4) {
                a0 = add2(a0, pr[3 * m]);
                a1 = add2(a1, pr[3 * (m + 1)]);
                a2 = add2(a2, pr[3 * (m + 2)]);
                a3 = add2(a3, pr[3 * (m + 3)]);
            }
            const F2 t = add2(add2(a0, a1), add2(a2, a3));
            float lo, hi;
            upk2(t, lo, hi);
            outb0[s0i * 3 + tid] = lo;
            outb1[s0i * 3 + tid] = hi;
        }
        __syncthreads();
    }
}

extern "C" void kernel_launch(void* const* d_in, const int* in_sizes, int n_in,
                              void* d_out, int out_size) {
    const float* x  = (const float*)d_in[0];
    const float* W1 = (const float*)d_in[1];
    const float* W2 = (const float*)d_in[2];
    prnn_kernel<<<Bb / 2, TPB>>>(x, W1, W2, (float*)d_out);
}

// round 6
// speedup vs baseline: 1.1363x; 1.1363x over previous
#include <cuda_runtime.h>

// PRNN_1769526526374: J2 plane-strain plasticity RNN.
// R6 = R5 with dynamic shared memory (49.4 KB > 48 KB static limit).
// 4 batch elements per thread: two f32x2 packed pairs sharing one set of
// packed W1/W2 registers -> 2x ILP, halved per-batch weight cost. Cached
// hardening term refreshed by first-order correction (2 exps per plastic
// lane-step). T=4 chunked reduction over 96 threads with shfl finish.

namespace {
constexpr int Bb   = 4096;
constexpr int Ss   = 512;
constexpr int TPB  = 128;
constexpr int T    = 4;     // steps per reduction chunk
constexpr int ROWF = 388;   // F2 per part row (padded for reduce banks)
constexpr int SX_F2   = 2 * Ss * 3;          // 3072 F2
constexpr int PART_F2 = 2 * T * ROWF;        // 3104 F2
constexpr int SMEM_BYTES = (SX_F2 + PART_F2) * 8;   // 49408 B

typedef unsigned long long F2;

__device__ __forceinline__ F2 pk2(float lo, float hi) {
    F2 r; asm("mov.b64 %0, {%1, %2};" : "=l"(r) : "f"(lo), "f"(hi)); return r;
}
__device__ __forceinline__ void upk2(F2 v, float& lo, float& hi) {
    asm("mov.b64 {%0, %1}, %2;" : "=f"(lo), "=f"(hi) : "l"(v));
}
__device__ __forceinline__ F2 mul2(F2 a, F2 b) {
    F2 r; asm("mul.rn.f32x2 %0, %1, %2;" : "=l"(r) : "l"(a), "l"(b)); return r;
}
__device__ __forceinline__ F2 add2(F2 a, F2 b) {
    F2 r; asm("add.rn.f32x2 %0, %1, %2;" : "=l"(r) : "l"(a), "l"(b)); return r;
}
__device__ __forceinline__ F2 fma2(F2 a, F2 b, F2 c) {
    F2 r; asm("fma.rn.f32x2 %0, %1, %2, %3;" : "=l"(r) : "l"(a), "l"(b), "l"(c)); return r;
}
} // namespace

__global__ void __launch_bounds__(TPB, 4) prnn_kernel(
    const float* __restrict__ x,    // [B,S,3]
    const float* __restrict__ W1,   // [384,3]
    const float* __restrict__ W2,   // [3,384]
    float* __restrict__ out)        // [B,S,3]
{
    extern __shared__ F2 dyn[];
    F2* sx0  = dyn;                 // pair 0 packed x, [Ss*3]
    F2* sx1  = dyn + Ss * 3;        // pair 1 packed x, [Ss*3]
    F2* part = dyn + SX_F2;         // [2][T][ROWF]

    const float MUv      = (float)(3130.0 / (2.0 * 1.3));
    const float TWO_MU   = 2.0f * MUv;
    const float THREE_MU = 3.0f * MUv;
    const float LAM      = (float)(3130.0 * 0.3 / (1.3 * 0.4));
    const float Kb       = LAM + (2.0f / 3.0f) * MUv;
    const float Ah = 64.8f, Bh = 33.6f;
    const float INV_C = (float)(1.0 / 0.003407);
    const float BC    = (float)(33.6 / 0.003407);

    const F2 MU2  = pk2(MUv, MUv);
    const F2 TMU2 = pk2(TWO_MU, TWO_MU);
    const F2 NTT2 = pk2(-TWO_MU / 3.0f, -TWO_MU / 3.0f);
    const F2 K2   = pk2(Kb, Kb);
    const F2 C15  = pk2(1.5f, 1.5f);
    const F2 C3   = pk2(3.0f, 3.0f);

    const int tid = threadIdx.x;
    const int t3  = 3 * tid;
    const int b0  = 4 * blockIdx.x;

    const float* xb = x + (long)b0 * (Ss * 3);
    for (int i = tid; i < Ss * 3; i += TPB) {
        sx0[i] = pk2(xb[i],              xb[i + Ss * 3]);
        sx1[i] = pk2(xb[i + 2 * Ss * 3], xb[i + 3 * Ss * 3]);
    }

    // Packed weights, shared by both pairs (amortized over 4 batches).
    F2 w1p[9], w2p[9];
#pragma unroll
    for (int i = 0; i < 9; ++i) { float w = W1[tid * 9 + i]; w1p[i] = pk2(w, w); }
#pragma unroll
    for (int o = 0; o < 3; ++o)
#pragma unroll
        for (int j = 0; j < 3; ++j) {
            float w = W2[o * 384 + t3 + j];
            w2p[o * 3 + j] = pk2(w, w);
        }

    // State per pair: ts_i = -2mu*ep_i packed; per half: kappa, bexm.
    F2 ts[2][4];
#pragma unroll
    for (int p = 0; p < 2; ++p)
#pragma unroll
        for (int i = 0; i < 4; ++i) ts[p][i] = 0;
    float kap[4]  = {0.f, 0.f, 0.f, 0.f};
    float bexm[4] = {Bh - Ah, Bh - Ah, Bh - Ah, Bh - Ah};

    float* ob = out + (long)b0 * (Ss * 3);

    __syncthreads();

    for (int s0i = 0; s0i < Ss; s0i += T) {
#pragma unroll 2
        for (int si = 0; si < T; ++si) {
            const int s = s0i + si;
#pragma unroll
            for (int p = 0; p < 2; ++p) {
                const F2* sxp = p ? sx1 : sx0;
                const F2 x0 = sxp[3 * s + 0];
                const F2 x1 = sxp[3 * s + 1];
                const F2 x2 = sxp[3 * s + 2];

                // fc1
                const F2 e0 = fma2(w1p[0], x0, fma2(w1p[1], x1, mul2(w1p[2], x2)));
                const F2 e1 = fma2(w1p[3], x0, fma2(w1p[4], x1, mul2(w1p[5], x2)));
                const F2 g2 = fma2(w1p[6], x0, fma2(w1p[7], x1, mul2(w1p[8], x2)));

                // deviatoric trial stress
                const F2 tr  = add2(e0, e1);
                const F2 ptr = mul2(NTT2, tr);
                F2 s0d = fma2(TMU2, e0, add2(ts[p][0], ptr));
                F2 s1d = fma2(TMU2, e1, add2(ts[p][1], ptr));
                F2 s2d = add2(ts[p][2], ptr);
                F2 s3d = fma2(MU2, g2, ts[p][3]);
                const F2 pr2 = mul2(K2, tr);

                F2 acc = mul2(s0d, s0d);
                acc = fma2(s1d, s1d, acc);
                acc = fma2(s2d, s2d, acc);
                const F2 qsq2 = fma2(C15, acc, mul2(C3, mul2(s3d, s3d)));

                float qsA, qsB;
                upk2(qsq2, qsA, qsB);
                qsA = fmaxf(qsA, 1e-24f);
                qsB = fmaxf(qsB, 1e-24f);
                const float rqA = rsqrtf(qsA);
                const float rqB = rsqrtf(qsB);
                const float qA  = qsA * rqA;
                const float qB  = qsB * rqB;

                const float bxA = bexm[2 * p], bxB = bexm[2 * p + 1];
                const float fA = qA + bxA;
                const float fB = qB + bxB;

                if (__any_sync(0xffffffffu, (fA > 0.f) | (fB > 0.f))) {
                    const float kA = kap[2 * p], kB = kap[2 * p + 1];
                    // seed = exact first Newton step via cached bex (no exp)
                    float dgA = __fdividef(fmaxf(fA, 0.f),
                                           THREE_MU + (bxA + Ah) * INV_C);
                    float dgB = __fdividef(fmaxf(fB, 0.f),
                                           THREE_MU + (bxB + Ah) * INV_C);
                    // iter 1
                    float ekA = __expf(-(kA + dgA) * INV_C);
                    float ekB = __expf(-(kB + dgB) * INV_C);
                    float rA  = qA - THREE_MU * dgA - Ah + Bh * ekA;
                    float rB  = qB - THREE_MU * dgB - Ah + Bh * ekB;
                    dgA = fmaxf(dgA + __fdividef(rA, THREE_MU + BC * ekA), 0.f);
                    dgB = fmaxf(dgB + __fdividef(rB, THREE_MU + BC * ekB), 0.f);
                    // iter 2 (quadratic -> past f32 precision)
                    ekA = __expf(-(kA + dgA) * INV_C);
                    ekB = __expf(-(kB + dgB) * INV_C);
                    const float dgpA = dgA, dgpB = dgB;
                    rA = qA - THREE_MU * dgA - Ah + Bh * ekA;
                    rB = qB - THREE_MU * dgB - Ah + Bh * ekB;
                    dgA = fmaxf(dgA + __fdividef(rA, THREE_MU + BC * ekA), 0.f);
                    dgB = fmaxf(dgB + __fdividef(rB, THREE_MU + BC * ekB), 0.f);

                    kap[2 * p]     = kA + dgA;
                    kap[2 * p + 1] = kB + dgB;
                    // refresh cached bex by 1st-order exp correction (no 3rd exp)
                    bexm[2 * p]     = Bh * ekA * (1.f - (dgA - dgpA) * INV_C) - Ah;
                    bexm[2 * p + 1] = Bh * ekB * (1.f - (dgB - dgpB) * INV_C) - Ah;

                    const F2 NN2 = pk2(-THREE_MU * dgA * rqA,
                                       -THREE_MU * dgB * rqB);
                    ts[p][0] = fma2(NN2, s0d, ts[p][0]);
                    ts[p][1] = fma2(NN2, s1d, ts[p][1]);
                    ts[p][2] = fma2(NN2, s2d, ts[p][2]);
                    ts[p][3] = fma2(NN2, s3d, ts[p][3]);
                    s0d = fma2(NN2, s0d, s0d);
                    s1d = fma2(NN2, s1d, s1d);
                    s3d = fma2(NN2, s3d, s3d);
                }

                const F2 sig0 = add2(s0d, pr2);
                const F2 sig1 = add2(s1d, pr2);

                F2* prp = part + (p * T + si) * ROWF + t3;
                prp[0] = fma2(w2p[0], sig0, fma2(w2p[1], sig1, mul2(w2p[2], s3d)));
                prp[1] = fma2(w2p[3], sig0, fma2(w2p[4], sig1, mul2(w2p[5], s3d)));
                prp[2] = fma2(w2p[6], sig0, fma2(w2p[7], sig1, mul2(w2p[8], s3d)));
            }
        }
        __syncthreads();

        // Reduction: 24 items (pair, si, o) x 4 lanes; each lane sums 32 F2,
        // then 2-stage shfl within the 4-lane group; lane0 writes 2 floats.
        if (tid < 96) {
            const int item = tid >> 2;
            const int l4   = tid & 3;
            const int pair = item / 12;
            const int rem  = item - 12 * pair;
            const int si   = rem / 3;
            const int o    = rem - 3 * si;
            const F2* prp = part + (pair * T + si) * ROWF + o + 3 * l4;
            F2 a0 = 0, a1 = 0, a2 = 0, a3 = 0;
#pragma unroll
            for (int j = 0; j < 32; j += 4) {
                a0 = add2(a0, prp[12 * j]);
                a1 = add2(a1, prp[12 * (j + 1)]);
                a2 = add2(a2, prp[12 * (j + 2)]);
                a3 = add2(a3, prp[12 * (j + 3)]);
            }
            const F2 t = add2(add2(a0, a1), add2(a2, a3));
            float lo, hi;
            upk2(t, lo, hi);
            lo += __shfl_xor_sync(0xffffffffu, lo, 1);
            hi += __shfl_xor_sync(0xffffffffu, hi, 1);
            lo += __shfl_xor_sync(0xffffffffu, lo, 2);
            hi += __shfl_xor_sync(0xffffffffu, hi, 2);
            if (l4 == 0) {
                const int idx = (s0i + si) * 3 + o;
                ob[(long)(2 * pair) * (Ss * 3) + idx]     = lo;
                ob[(long)(2 * pair + 1) * (Ss * 3) + idx] = hi;
            }
        }
        __syncthreads();
    }
}

extern "C" void kernel_launch(void* const* d_in, const int* in_sizes, int n_in,
                              void* d_out, int out_size) {
    const float* x  = (const float*)d_in[0];
    const float* W1 = (const float*)d_in[1];
    const float* W2 = (const float*)d_in[2];
    // Opt-in to >48KB dynamic smem. Not an allocation; idempotent and
    // graph-capture-safe (attribute set, no stream operation).
    cudaFuncSetAttribute(prnn_kernel,
                         cudaFuncAttributeMaxDynamicSharedMemorySize,
                         SMEM_BYTES);
    prnn_kernel<<<Bb / 4, TPB, SMEM_BYTES>>>(x, W1, W2, (float*)d_out);
}

// round 10
// speedup vs baseline: 1.2220x; 1.0755x over previous
#include <cuda_runtime.h>

// PRNN_1769526526374: J2 plane-strain plasticity RNN.
// R10 = R6 skeleton (proven: dynamic smem, T=4 chunk reduction with 96
// fully-valid threads) + compute-path diet only:
//  - branchless Newton return mapping (elastic lanes are algebraic no-ops;
//    expf(0)==1 keeps cached state invariant)
//  - no kappa (multiplicative bex update), no ts2/s2d (tracelessness:
//    qsq = 3*(s0^2+s0*s1+s1^2+s3^2); ts2 = -(ts0+ts1) is auto-maintained)

namespace {
constexpr int Bb   = 4096;
constexpr int Ss   = 512;
constexpr int TPB  = 128;
constexpr int T    = 4;     // steps per reduction chunk
constexpr int ROWF = 388;   // F2 per part row (padded for reduce banks)
constexpr int SX_F2   = 2 * Ss * 3;          // 3072 F2
constexpr int PART_F2 = 2 * T * ROWF;        // 3104 F2
constexpr int SMEM_BYTES = (SX_F2 + PART_F2) * 8;   // 49408 B

typedef unsigned long long F2;

__device__ __forceinline__ F2 pk2(float lo, float hi) {
    F2 r; asm("mov.b64 %0, {%1, %2};" : "=l"(r) : "f"(lo), "f"(hi)); return r;
}
__device__ __forceinline__ void upk2(F2 v, float& lo, float& hi) {
    asm("mov.b64 {%0, %1}, %2;" : "=f"(lo), "=f"(hi) : "l"(v));
}
__device__ __forceinline__ F2 mul2(F2 a, F2 b) {
    F2 r; asm("mul.rn.f32x2 %0, %1, %2;" : "=l"(r) : "l"(a), "l"(b)); return r;
}
__device__ __forceinline__ F2 add2(F2 a, F2 b) {
    F2 r; asm("add.rn.f32x2 %0, %1, %2;" : "=l"(r) : "l"(a), "l"(b)); return r;
}
__device__ __forceinline__ F2 fma2(F2 a, F2 b, F2 c) {
    F2 r; asm("fma.rn.f32x2 %0, %1, %2, %3;" : "=l"(r) : "l"(a), "l"(b), "l"(c)); return r;
}
} // namespace

__global__ void __launch_bounds__(TPB, 4) prnn_kernel(
    const float* __restrict__ x,    // [B,S,3]
    const float* __restrict__ W1,   // [384,3]
    const float* __restrict__ W2,   // [3,384]
    float* __restrict__ out)        // [B,S,3]
{
    extern __shared__ F2 dyn[];
    F2* sx0  = dyn;                 // pair 0 packed x, [Ss*3]
    F2* sx1  = dyn + Ss * 3;        // pair 1 packed x, [Ss*3]
    F2* part = dyn + SX_F2;         // [2][T][ROWF]

    const float MUv      = (float)(3130.0 / (2.0 * 1.3));
    const float TWO_MU   = 2.0f * MUv;
    const float THREE_MU = 3.0f * MUv;
    const float NEG3MU   = -THREE_MU;
    const float LAM      = (float)(3130.0 * 0.3 / (1.3 * 0.4));
    const float Kb       = LAM + (2.0f / 3.0f) * MUv;
    const float Ah = 64.8f, Bh = 33.6f;
    const float INV_C  = (float)(1.0 / 0.003407);
    const float NINV_C = -INV_C;

    const F2 MU2  = pk2(MUv, MUv);
    const F2 TMU2 = pk2(TWO_MU, TWO_MU);
    const F2 NTT2 = pk2(-TWO_MU / 3.0f, -TWO_MU / 3.0f);
    const F2 K2   = pk2(Kb, Kb);
    const F2 C3   = pk2(3.0f, 3.0f);

    const int tid = threadIdx.x;
    const int t3  = 3 * tid;
    const int b0  = 4 * blockIdx.x;

    const float* xb = x + (long)b0 * (Ss * 3);
    for (int i = tid; i < Ss * 3; i += TPB) {
        sx0[i] = pk2(xb[i],              xb[i + Ss * 3]);
        sx1[i] = pk2(xb[i + 2 * Ss * 3], xb[i + 3 * Ss * 3]);
    }

    // Packed weights, shared by both pairs (amortized over 4 batches).
    F2 w1p[9], w2p[9];
#pragma unroll
    for (int i = 0; i < 9; ++i) { float w = W1[tid * 9 + i]; w1p[i] = pk2(w, w); }
#pragma unroll
    for (int o = 0; o < 3; ++o)
#pragma unroll
        for (int j = 0; j < 3; ++j) {
            float w = W2[o * 384 + t3 + j];
            w2p[o * 3 + j] = pk2(w, w);
        }

    // State: ts_i = -2mu*ep_i for i in {xx,yy,xy} (zz via tracelessness);
    // bex = B*exp(-kappa/C) per half (kappa itself never materialized).
    F2 ts[2][3];
#pragma unroll
    for (int p = 0; p < 2; ++p)
#pragma unroll
        for (int i = 0; i < 3; ++i) ts[p][i] = 0;
    float bex[4] = {Bh, Bh, Bh, Bh};

    float* ob = out + (long)b0 * (Ss * 3);

    __syncthreads();

    for (int s0i = 0; s0i < Ss; s0i += T) {
#pragma unroll 2
        for (int si = 0; si < T; ++si) {
            const int s = s0i + si;
#pragma unroll
            for (int p = 0; p < 2; ++p) {
                const F2* sxp = p ? sx1 : sx0;
                const F2 x0 = sxp[3 * s + 0];
                const F2 x1 = sxp[3 * s + 1];
                const F2 x2 = sxp[3 * s + 2];

                // fc1
                const F2 e0 = fma2(w1p[0], x0, fma2(w1p[1], x1, mul2(w1p[2], x2)));
                const F2 e1 = fma2(w1p[3], x0, fma2(w1p[4], x1, mul2(w1p[5], x2)));
                const F2 g2 = fma2(w1p[6], x0, fma2(w1p[7], x1, mul2(w1p[8], x2)));

                // deviatoric trial (zz implied by tracelessness)
                const F2 tr  = add2(e0, e1);
                const F2 ptr = mul2(NTT2, tr);
                F2 s0d = fma2(TMU2, e0, add2(ts[p][0], ptr));
                F2 s1d = fma2(TMU2, e1, add2(ts[p][1], ptr));
                F2 s3d = fma2(MU2, g2, ts[p][2]);
                const F2 pr2 = mul2(K2, tr);

                // qsq = 3*(s0^2 + s0*s1 + s1^2 + s3^2)
                F2 acc = mul2(s3d, s3d);
                acc = fma2(s1d, s1d, acc);
                acc = fma2(s0d, s1d, acc);
                acc = fma2(s0d, s0d, acc);
                const F2 qsq2 = mul2(C3, acc);

                float qsA, qsB;
                upk2(qsq2, qsA, qsB);
                qsA = fmaxf(qsA, 1e-24f);
                qsB = fmaxf(qsB, 1e-24f);
                const float rqA = rsqrtf(qsA);
                const float rqB = rsqrtf(qsB);
                const float qaA = qsA * rqA - Ah;   // q - A
                const float qaB = qsB * rqB - Ah;

                const float bxA = bex[2 * p], bxB = bex[2 * p + 1];
                const float fA = qaA + bxA;
                const float fB = qaB + bxB;

                // Branchless return mapping. Elastic lanes: seed = 0, residual
                // <= 0, dg pinned at 0 by fmax; expf(0)==1 keeps bex invariant.
                // Plastic lanes: exact first Newton step + 2 iterations
                // (quadratic -> past f32 precision, same root as reference).
                float dgA = __fdividef(fmaxf(fA, 0.f), fmaf(bxA, INV_C, THREE_MU));
                float dgB = __fdividef(fmaxf(fB, 0.f), fmaf(bxB, INV_C, THREE_MU));
                // iter 1
                float BekA = bxA * __expf(dgA * NINV_C);
                float BekB = bxB * __expf(dgB * NINV_C);
                float rA = fmaf(NEG3MU, dgA, qaA) + BekA;
                float rB = fmaf(NEG3MU, dgB, qaB) + BekB;
                dgA = fmaxf(dgA + __fdividef(rA, fmaf(BekA, INV_C, THREE_MU)), 0.f);
                dgB = fmaxf(dgB + __fdividef(rB, fmaf(BekB, INV_C, THREE_MU)), 0.f);
                // iter 2
                BekA = bxA * __expf(dgA * NINV_C);
                BekB = bxB * __expf(dgB * NINV_C);
                const float dg2A = dgA, dg2B = dgB;
                rA = fmaf(NEG3MU, dgA, qaA) + BekA;
                rB = fmaf(NEG3MU, dgB, qaB) + BekB;
                dgA = fmaxf(dgA + __fdividef(rA, fmaf(BekA, INV_C, THREE_MU)), 0.f);
                dgB = fmaxf(dgB + __fdividef(rB, fmaf(BekB, INV_C, THREE_MU)), 0.f);

                // cached hardening refresh: 1st-order exp correction (no 3rd exp)
                bex[2 * p]     = BekA * fmaf(dgA - dg2A, NINV_C, 1.f);
                bex[2 * p + 1] = BekB * fmaf(dgB - dg2B, NINV_C, 1.f);

                // radial return: one packed coefficient for stress AND state
                const F2 NN2 = pk2(NEG3MU * dgA * rqA, NEG3MU * dgB * rqB);
                ts[p][0] = fma2(NN2, s0d, ts[p][0]);
                ts[p][1] = fma2(NN2, s1d, ts[p][1]);
                ts[p][2] = fma2(NN2, s3d, ts[p][2]);
                s0d = fma2(NN2, s0d, s0d);
                s1d = fma2(NN2, s1d, s1d);
                s3d = fma2(NN2, s3d, s3d);

                const F2 sig0 = add2(s0d, pr2);
                const F2 sig1 = add2(s1d, pr2);

                F2* prp = part + (p * T + si) * ROWF + t3;
                prp[0] = fma2(w2p[0], sig0, fma2(w2p[1], sig1, mul2(w2p[2], s3d)));
                prp[1] = fma2(w2p[3], sig0, fma2(w2p[4], sig1, mul2(w2p[5], s3d)));
                prp[2] = fma2(w2p[6], sig0, fma2(w2p[7], sig1, mul2(w2p[8], s3d)));
            }
        }
        __syncthreads();

        // Reduction: 24 items (pair, si, o) x 4 lanes = 96 threads (3 full
        // warps, all slots valid); each lane sums 32 F2, then 2-stage shfl
        // within the 4-lane group; lane0 writes 2 floats.
        if (tid < 96) {
            const int item = tid >> 2;
            const int l4   = tid & 3;
            const int pair = item / 12;
            const int rem  = item - 12 * pair;
            const int si   = rem / 3;
            const int o    = rem - 3 * si;
            const F2* prp = part + (pair * T + si) * ROWF + o + 3 * l4;
            F2 a0 = 0, a1 = 0, a2 = 0, a3 = 0;
#pragma unroll
            for (int j = 0; j < 32; j += 4) {
                a0 = add2(a0, prp[12 * j]);
                a1 = add2(a1, prp[12 * (j + 1)]);
                a2 = add2(a2, prp[12 * (j + 2)]);
                a3 = add2(a3, prp[12 * (j + 3)]);
            }
            const F2 t = add2(add2(a0, a1), add2(a2, a3));
            float lo, hi;
            upk2(t, lo, hi);
            lo += __shfl_xor_sync(0xffffffffu, lo, 1);
            hi += __shfl_xor_sync(0xffffffffu, hi, 1);
            lo += __shfl_xor_sync(0xffffffffu, lo, 2);
            hi += __shfl_xor_sync(0xffffffffu, hi, 2);
            if (l4 == 0) {
                const int idx = (s0i + si) * 3 + o;
                ob[(long)(2 * pair) * (Ss * 3) + idx]     = lo;
                ob[(long)(2 * pair + 1) * (Ss * 3) + idx] = hi;
            }
        }
        __syncthreads();
    }
}

extern "C" void kernel_launch(void* const* d_in, const int* in_sizes, int n_in,
                              void* d_out, int out_size) {
    const float* x  = (const float*)d_in[0];
    const float* W1 = (const float*)d_in[1];
    const float* W2 = (const float*)d_in[2];
    // Opt-in to >48KB dynamic smem. Not an allocation; idempotent and
    // graph-capture-safe (attribute set, no stream operation).
    cudaFuncSetAttribute(prnn_kernel,
                         cudaFuncAttributeMaxDynamicSharedMemorySize,
                         SMEM_BYTES);
    prnn_kernel<<<Bb / 4, TPB, SMEM_BYTES>>>(x, W1, W2, (float*)d_out);
}

// round 11
// speedup vs baseline: 1.2300x; 1.0066x over previous
#include <cuda_runtime.h>

// PRNN_1769526526374: J2 plane-strain plasticity RNN.
// R11 = R10 compute path, occupancy push as the single change:
//  - T=2 chunks -> smem 37.0 KB (static again), part buffer halved
//  - __launch_bounds__(128, 5): regs forced <=102 -> 5 blocks/SM (RF-bound)
//  - reduction: 12 items x 8 lanes = 96 threads (3 FULL warps, all valid),
//    16 F2 per lane + 3-stage shfl

namespace {
constexpr int Bb   = 4096;
constexpr int Ss   = 512;
constexpr int TPB  = 128;
constexpr int T    = 2;     // steps per reduction chunk
constexpr int ROWF = 388;   // F2 per part row (padded for reduce banks)

typedef unsigned long long F2;

__device__ __forceinline__ F2 pk2(float lo, float hi) {
    F2 r; asm("mov.b64 %0, {%1, %2};" : "=l"(r) : "f"(lo), "f"(hi)); return r;
}
__device__ __forceinline__ void upk2(F2 v, float& lo, float& hi) {
    asm("mov.b64 {%0, %1}, %2;" : "=f"(lo), "=f"(hi) : "l"(v));
}
__device__ __forceinline__ F2 mul2(F2 a, F2 b) {
    F2 r; asm("mul.rn.f32x2 %0, %1, %2;" : "=l"(r) : "l"(a), "l"(b)); return r;
}
__device__ __forceinline__ F2 add2(F2 a, F2 b) {
    F2 r; asm("add.rn.f32x2 %0, %1, %2;" : "=l"(r) : "l"(a), "l"(b)); return r;
}
__device__ __forceinline__ F2 fma2(F2 a, F2 b, F2 c) {
    F2 r; asm("fma.rn.f32x2 %0, %1, %2, %3;" : "=l"(r) : "l"(a), "l"(b), "l"(c)); return r;
}
} // namespace

__global__ void __launch_bounds__(TPB, 5) prnn_kernel(
    const float* __restrict__ x,    // [B,S,3]
    const float* __restrict__ W1,   // [384,3]
    const float* __restrict__ W2,   // [3,384]
    float* __restrict__ out)        // [B,S,3]
{
    const float MUv      = (float)(3130.0 / (2.0 * 1.3));
    const float TWO_MU   = 2.0f * MUv;
    const float THREE_MU = 3.0f * MUv;
    const float NEG3MU   = -THREE_MU;
    const float LAM      = (float)(3130.0 * 0.3 / (1.3 * 0.4));
    const float Kb       = LAM + (2.0f / 3.0f) * MUv;
    const float Ah = 64.8f, Bh = 33.6f;
    const float INV_C  = (float)(1.0 / 0.003407);
    const float NINV_C = -INV_C;

    const F2 MU2  = pk2(MUv, MUv);
    const F2 TMU2 = pk2(TWO_MU, TWO_MU);
    const F2 NTT2 = pk2(-TWO_MU / 3.0f, -TWO_MU / 3.0f);
    const F2 K2   = pk2(Kb, Kb);
    const F2 C3   = pk2(3.0f, 3.0f);

    __shared__ F2 sx0[Ss * 3];          // 12.3 KB
    __shared__ F2 sx1[Ss * 3];          // 12.3 KB
    __shared__ F2 part[2 * T * ROWF];   // 12.4 KB

    const int tid = threadIdx.x;
    const int t3  = 3 * tid;
    const int b0  = 4 * blockIdx.x;

    const float* xb = x + (long)b0 * (Ss * 3);
    for (int i = tid; i < Ss * 3; i += TPB) {
        sx0[i] = pk2(xb[i],              xb[i + Ss * 3]);
        sx1[i] = pk2(xb[i + 2 * Ss * 3], xb[i + 3 * Ss * 3]);
    }

    // Packed weights, shared by both pairs (amortized over 4 batches).
    F2 w1p[9], w2p[9];
#pragma unroll
    for (int i = 0; i < 9; ++i) { float w = W1[tid * 9 + i]; w1p[i] = pk2(w, w); }
#pragma unroll
    for (int o = 0; o < 3; ++o)
#pragma unroll
        for (int j = 0; j < 3; ++j) {
            float w = W2[o * 384 + t3 + j];
            w2p[o * 3 + j] = pk2(w, w);
        }

    // State: ts_i = -2mu*ep_i for i in {xx,yy,xy} (zz via tracelessness);
    // bex = B*exp(-kappa/C) per half (kappa itself never materialized).
    F2 ts[2][3];
#pragma unroll
    for (int p = 0; p < 2; ++p)
#pragma unroll
        for (int i = 0; i < 3; ++i) ts[p][i] = 0;
    float bex[4] = {Bh, Bh, Bh, Bh};

    float* ob = out + (long)b0 * (Ss * 3);

    __syncthreads();

    for (int s0i = 0; s0i < Ss; s0i += T) {
#pragma unroll
        for (int si = 0; si < T; ++si) {
            const int s = s0i + si;
#pragma unroll
            for (int p = 0; p < 2; ++p) {
                const F2* sxp = p ? sx1 : sx0;
                const F2 x0 = sxp[3 * s + 0];
                const F2 x1 = sxp[3 * s + 1];
                const F2 x2 = sxp[3 * s + 2];

                // fc1
                const F2 e0 = fma2(w1p[0], x0, fma2(w1p[1], x1, mul2(w1p[2], x2)));
                const F2 e1 = fma2(w1p[3], x0, fma2(w1p[4], x1, mul2(w1p[5], x2)));
                const F2 g2 = fma2(w1p[6], x0, fma2(w1p[7], x1, mul2(w1p[8], x2)));

                // deviatoric trial (zz implied by tracelessness)
                const F2 tr  = add2(e0, e1);
                const F2 ptr = mul2(NTT2, tr);
                F2 s0d = fma2(TMU2, e0, add2(ts[p][0], ptr));
                F2 s1d = fma2(TMU2, e1, add2(ts[p][1], ptr));
                F2 s3d = fma2(MU2, g2, ts[p][2]);
                const F2 pr2 = mul2(K2, tr);

                // qsq = 3*(s0^2 + s0*s1 + s1^2 + s3^2)
                F2 acc = mul2(s3d, s3d);
                acc = fma2(s1d, s1d, acc);
                acc = fma2(s0d, s1d, acc);
                acc = fma2(s0d, s0d, acc);
                const F2 qsq2 = mul2(C3, acc);

                float qsA, qsB;
                upk2(qsq2, qsA, qsB);
                qsA = fmaxf(qsA, 1e-24f);
                qsB = fmaxf(qsB, 1e-24f);
                const float rqA = rsqrtf(qsA);
                const float rqB = rsqrtf(qsB);
                const float qaA = qsA * rqA - Ah;   // q - A
                const float qaB = qsB * rqB - Ah;

                const float bxA = bex[2 * p], bxB = bex[2 * p + 1];
                const float fA = qaA + bxA;
                const float fB = qaB + bxB;

                // Branchless return mapping. Elastic lanes: seed = 0, residual
                // <= 0, dg pinned at 0 by fmax; expf(0)==1 keeps bex invariant.
                // Plastic lanes: exact first Newton step + 2 iterations
                // (quadratic -> past f32 precision, same root as reference).
                float dgA = __fdividef(fmaxf(fA, 0.f), fmaf(bxA, INV_C, THREE_MU));
                float dgB = __fdividef(fmaxf(fB, 0.f), fmaf(bxB, INV_C, THREE_MU));
                // iter 1
                float BekA = bxA * __expf(dgA * NINV_C);
                float BekB = bxB * __expf(dgB * NINV_C);
                float rA = fmaf(NEG3MU, dgA, qaA) + BekA;
                float rB = fmaf(NEG3MU, dgB, qaB) + BekB;
                dgA = fmaxf(dgA + __fdividef(rA, fmaf(BekA, INV_C, THREE_MU)), 0.f);
                dgB = fmaxf(dgB + __fdividef(rB, fmaf(BekB, INV_C, THREE_MU)), 0.f);
                // iter 2
                BekA = bxA * __expf(dgA * NINV_C);
                BekB = bxB * __expf(dgB * NINV_C);
                const float dg2A = dgA, dg2B = dgB;
                rA = fmaf(NEG3MU, dgA, qaA) + BekA;
                rB = fmaf(NEG3MU, dgB, qaB) + BekB;
                dgA = fmaxf(dgA + __fdividef(rA, fmaf(BekA, INV_C, THREE_MU)), 0.f);
                dgB = fmaxf(dgB + __fdividef(rB, fmaf(BekB, INV_C, THREE_MU)), 0.f);

                // cached hardening refresh: 1st-order exp correction (no 3rd exp)
                bex[2 * p]     = BekA * fmaf(dgA - dg2A, NINV_C, 1.f);
                bex[2 * p + 1] = BekB * fmaf(dgB - dg2B, NINV_C, 1.f);

                // radial return: one packed coefficient for stress AND state
                const F2 NN2 = pk2(NEG3MU * dgA * rqA, NEG3MU * dgB * rqB);
                ts[p][0] = fma2(NN2, s0d, ts[p][0]);
                ts[p][1] = fma2(NN2, s1d, ts[p][1]);
                ts[p][2] = fma2(NN2, s3d, ts[p][2]);
                s0d = fma2(NN2, s0d, s0d);
                s1d = fma2(NN2, s1d, s1d);
                s3d = fma2(NN2, s3d, s3d);

                const F2 sig0 = add2(s0d, pr2);
                const F2 sig1 = add2(s1d, pr2);

                F2* prp = part + (p * T + si) * ROWF + t3;
                prp[0] = fma2(w2p[0], sig0, fma2(w2p[1], sig1, mul2(w2p[2], s3d)));
                prp[1] = fma2(w2p[3], sig0, fma2(w2p[4], sig1, mul2(w2p[5], s3d)));
                prp[2] = fma2(w2p[6], sig0, fma2(w2p[7], sig1, mul2(w2p[8], s3d)));
            }
        }
        __syncthreads();

        // Reduction: 12 items (pair, si, o) x 8 lanes = 96 threads (3 FULL
        // warps, every slot valid). Each lane sums 16 F2 (stride 8 points),
        // then 3-stage shfl within the 8-lane group; lane0 writes 2 floats.
        if (tid < 96) {
            const int item = tid >> 3;        // 0..11
            const int l8   = tid & 7;
            const int pair = item / (T * 3);
            const int rem  = item - (T * 3) * pair;
            const int si   = rem / 3;
            const int o    = rem - 3 * si;
            const F2* prp = part + (pair * T + si) * ROWF + o + 3 * l8;
            F2 a0 = 0, a1 = 0, a2 = 0, a3 = 0;
#pragma unroll
            for (int j = 0; j < 16; j += 4) {
                a0 = add2(a0, prp[24 * j]);
                a1 = add2(a1, prp[24 * (j + 1)]);
                a2 = add2(a2, prp[24 * (j + 2)]);
                a3 = add2(a3, prp[24 * (j + 3)]);
            }
            const F2 t = add2(add2(a0, a1), add2(a2, a3));
            float lo, hi;
            upk2(t, lo, hi);
            lo += __shfl_xor_sync(0xffffffffu, lo, 1);
            hi += __shfl_xor_sync(0xffffffffu, hi, 1);
            lo += __shfl_xor_sync(0xffffffffu, lo, 2);
            hi += __shfl_xor_sync(0xffffffffu, hi, 2);
            lo += __shfl_xor_sync(0xffffffffu, lo, 4);
            hi += __shfl_xor_sync(0xffffffffu, hi, 4);
            if ((tid & 7) == 0) {
                const int idx = (s0i + si) * 3 + o;
                ob[(long)(2 * pair) * (Ss * 3) + idx]     = lo;
                ob[(long)(2 * pair + 1) * (Ss * 3) + idx] = hi;
            }
        }
        __syncthreads();
    }
}

extern "C" void kernel_launch(void* const* d_in, const int* in_sizes, int n_in,
                              void* d_out, int out_size) {
    const float* x  = (const float*)d_in[0];
    const float* W1 = (const float*)d_in[1];
    const float* W2 = (const float*)d_in[2];
    prnn_kernel<<<Bb / 4, TPB>>>(x, W1, W2, (float*)d_out);
}

// round 13
// speedup vs baseline: 1.2803x; 1.0408x over previous
#include <cuda_runtime.h>

// PRNN_1769526526374: J2 plane-strain plasticity RNN.
// R13 = R12 with the state-update SIGN BUG fixed:
//   bex_new = Bek * exp((dg0 - dg)/C)   [R12 had exp((dg - dg0)/C) -> 5e-2 err]
// Return mapping: seed via cached reciprocal denominator (no MUFU) + ONE
// guarded Halley iteration (cubic). 5 MUFU per half per step vs 6, and the
// critical path loses seed-rcp + one exp + one rcp. Guards: Halley
// denominator floored at d^2; dg clamped to [0, dg0 + r/(3mu)].

namespace {
constexpr int Bb   = 4096;
constexpr int Ss   = 512;
constexpr int TPB  = 128;
constexpr int T    = 2;     // steps per reduction chunk
constexpr int ROWF = 388;   // F2 per part row (padded for reduce banks)

typedef unsigned long long F2;

__device__ __forceinline__ F2 pk2(float lo, float hi) {
    F2 r; asm("mov.b64 %0, {%1, %2};" : "=l"(r) : "f"(lo), "f"(hi)); return r;
}
__device__ __forceinline__ void upk2(F2 v, float& lo, float& hi) {
    asm("mov.b64 {%0, %1}, %2;" : "=f"(lo), "=f"(hi) : "l"(v));
}
__device__ __forceinline__ F2 mul2(F2 a, F2 b) {
    F2 r; asm("mul.rn.f32x2 %0, %1, %2;" : "=l"(r) : "l"(a), "l"(b)); return r;
}
__device__ __forceinline__ F2 add2(F2 a, F2 b) {
    F2 r; asm("add.rn.f32x2 %0, %1, %2;" : "=l"(r) : "l"(a), "l"(b)); return r;
}
__device__ __forceinline__ F2 fma2(F2 a, F2 b, F2 c) {
    F2 r; asm("fma.rn.f32x2 %0, %1, %2, %3;" : "=l"(r) : "l"(a), "l"(b), "l"(c)); return r;
}
} // namespace

__global__ void __launch_bounds__(TPB, 5) prnn_kernel(
    const float* __restrict__ x,    // [B,S,3]
    const float* __restrict__ W1,   // [384,3]
    const float* __restrict__ W2,   // [3,384]
    float* __restrict__ out)        // [B,S,3]
{
    const float MUv      = (float)(3130.0 / (2.0 * 1.3));
    const float TWO_MU   = 2.0f * MUv;
    const float THREE_MU = 3.0f * MUv;
    const float NEG3MU   = -THREE_MU;
    const float INV3MU   = 1.0f / THREE_MU;
    const float LAM      = (float)(3130.0 * 0.3 / (1.3 * 0.4));
    const float Kb       = LAM + (2.0f / 3.0f) * MUv;
    const float Ah = 64.8f, Bh = 33.6f;
    const float INV_C  = (float)(1.0 / 0.003407);
    const float NINV_C = -INV_C;
    const float INVC2  = INV_C * INV_C;      // 1/C^2

    const F2 MU2  = pk2(MUv, MUv);
    const F2 TMU2 = pk2(TWO_MU, TWO_MU);
    const F2 NTT2 = pk2(-TWO_MU / 3.0f, -TWO_MU / 3.0f);
    const F2 K2   = pk2(Kb, Kb);
    const F2 C3   = pk2(3.0f, 3.0f);

    __shared__ F2 sx0[Ss * 3];          // 12.3 KB
    __shared__ F2 sx1[Ss * 3];          // 12.3 KB
    __shared__ F2 part[2 * T * ROWF];   // 12.4 KB

    const int tid = threadIdx.x;
    const int t3  = 3 * tid;
    const int b0  = 4 * blockIdx.x;

    const float* xb = x + (long)b0 * (Ss * 3);
    for (int i = tid; i < Ss * 3; i += TPB) {
        sx0[i] = pk2(xb[i],              xb[i + Ss * 3]);
        sx1[i] = pk2(xb[i + 2 * Ss * 3], xb[i + 3 * Ss * 3]);
    }

    // Packed weights, shared by both pairs (amortized over 4 batches).
    F2 w1p[9], w2p[9];
#pragma unroll
    for (int i = 0; i < 9; ++i) { float w = W1[tid * 9 + i]; w1p[i] = pk2(w, w); }
#pragma unroll
    for (int o = 0; o < 3; ++o)
#pragma unroll
        for (int j = 0; j < 3; ++j) {
            float w = W2[o * 384 + t3 + j];
            w2p[o * 3 + j] = pk2(w, w);
        }

    // State per half: bex = B*exp(-kappa/C); ivd = 1/(3mu + bex/C) (cached
    // seed denominator, refreshed off the critical path each step).
    // Packed: ts_i = -2mu*ep_i for i in {xx,yy,xy} (zz via tracelessness).
    F2 ts[2][3];
#pragma unroll
    for (int p = 0; p < 2; ++p)
#pragma unroll
        for (int i = 0; i < 3; ++i) ts[p][i] = 0;
    float bex[4], ivd[4];
    const float ivd0 = 1.0f / (THREE_MU + Bh * INV_C);
#pragma unroll
    for (int h = 0; h < 4; ++h) { bex[h] = Bh; ivd[h] = ivd0; }

    float* ob = out + (long)b0 * (Ss * 3);

    __syncthreads();

    for (int s0i = 0; s0i < Ss; s0i += T) {
#pragma unroll
        for (int si = 0; si < T; ++si) {
            const int s = s0i + si;
#pragma unroll
            for (int p = 0; p < 2; ++p) {
                const F2* sxp = p ? sx1 : sx0;
                const F2 x0 = sxp[3 * s + 0];
                const F2 x1 = sxp[3 * s + 1];
                const F2 x2 = sxp[3 * s + 2];

                // fc1
                const F2 e0 = fma2(w1p[0], x0, fma2(w1p[1], x1, mul2(w1p[2], x2)));
                const F2 e1 = fma2(w1p[3], x0, fma2(w1p[4], x1, mul2(w1p[5], x2)));
                const F2 g2 = fma2(w1p[6], x0, fma2(w1p[7], x1, mul2(w1p[8], x2)));

                // deviatoric trial (zz implied by tracelessness)
                const F2 tr  = add2(e0, e1);
                const F2 ptr = mul2(NTT2, tr);
                F2 s0d = fma2(TMU2, e0, add2(ts[p][0], ptr));
                F2 s1d = fma2(TMU2, e1, add2(ts[p][1], ptr));
                F2 s3d = fma2(MU2, g2, ts[p][2]);
                const F2 pr2 = mul2(K2, tr);

                // qsq = 3*(s0^2 + s0*s1 + s1^2 + s3^2)
                F2 acc = mul2(s3d, s3d);
                acc = fma2(s1d, s1d, acc);
                acc = fma2(s0d, s1d, acc);
                acc = fma2(s0d, s0d, acc);
                const F2 qsq2 = mul2(C3, acc);

                float qsA, qsB;
                upk2(qsq2, qsA, qsB);
                qsA = fmaxf(qsA, 1e-24f);
                qsB = fmaxf(qsB, 1e-24f);
                const float rqA = rsqrtf(qsA);
                const float rqB = rsqrtf(qsB);
                const float qaA = qsA * rqA - Ah;   // q - A
                const float qaB = qsB * rqB - Ah;

                const float bxA = bex[2 * p], bxB = bex[2 * p + 1];

                // Seed: exact first Newton step from 0 using CACHED reciprocal
                // denominator (no MUFU, no divide on the critical path).
                const float dg0A = fmaxf(qaA + bxA, 0.f) * ivd[2 * p];
                const float dg0B = fmaxf(qaB + bxB, 0.f) * ivd[2 * p + 1];

                // One guarded Halley iteration (cubic convergence).
                // f(dg) = qa - 3mu*dg + Bek; f' = -d, d = 3mu + Bek/C;
                // f'' = Bek/C^2. Halley: dg += 2 r d / (2 d^2 - r*Bek/C^2).
                const float BekA = bxA * __expf(dg0A * NINV_C);
                const float BekB = bxB * __expf(dg0B * NINV_C);
                const float dA = fmaf(BekA, INV_C, THREE_MU);
                const float dB = fmaf(BekB, INV_C, THREE_MU);
                const float rA = fmaf(NEG3MU, dg0A, qaA) + BekA;
                const float rB = fmaf(NEG3MU, dg0B, qaB) + BekB;
                float denA = fmaf(-rA * BekA, INVC2, 2.f * dA * dA);
                float denB = fmaf(-rB * BekB, INVC2, 2.f * dB * dB);
                denA = fmaxf(denA, dA * dA);   // guard: step <= 2x Newton
                denB = fmaxf(denB, dB * dB);
                float dgA = dg0A + __fdividef(2.f * rA * dA, denA);
                float dgB = dg0B + __fdividef(2.f * rB * dB, denB);
                // root upper bound: slope magnitude >= 3mu everywhere
                dgA = fminf(dgA, fmaf(rA, INV3MU, dg0A));
                dgB = fminf(dgB, fmaf(rB, INV3MU, dg0B));
                dgA = fmaxf(dgA, 0.f);
                dgB = fmaxf(dgB, 0.f);
                // (elastic lanes: dg0=0, r=f<=0 -> correction<=0 -> dg=0)

                // EXACT state update (sign fixed vs R12):
                // bex_new = bx*exp(-dg/C) = Bek*exp((dg0 - dg)/C).
                const float bexnA = BekA * __expf((dg0A - dgA) * INV_C);
                const float bexnB = BekB * __expf((dg0B - dgB) * INV_C);
                bex[2 * p]     = bexnA;
                bex[2 * p + 1] = bexnB;
                ivd[2 * p]     = __fdividef(1.f, fmaf(bexnA, INV_C, THREE_MU));
                ivd[2 * p + 1] = __fdividef(1.f, fmaf(bexnB, INV_C, THREE_MU));

                // radial return: one packed coefficient for stress AND state
                const F2 NN2 = pk2(NEG3MU * dgA * rqA, NEG3MU * dgB * rqB);
                ts[p][0] = fma2(NN2, s0d, ts[p][0]);
                ts[p][1] = fma2(NN2, s1d, ts[p][1]);
                ts[p][2] = fma2(NN2, s3d, ts[p][2]);
                s0d = fma2(NN2, s0d, s0d);
                s1d = fma2(NN2, s1d, s1d);
                s3d = fma2(NN2, s3d, s3d);

                const F2 sig0 = add2(s0d, pr2);
                const F2 sig1 = add2(s1d, pr2);

                F2* prp = part + (p * T + si) * ROWF + t3;
                prp[0] = fma2(w2p[0], sig0, fma2(w2p[1], sig1, mul2(w2p[2], s3d)));
                prp[1] = fma2(w2p[3], sig0, fma2(w2p[4], sig1, mul2(w2p[5], s3d)));
                prp[2] = fma2(w2p[6], sig0, fma2(w2p[7], sig1, mul2(w2p[8], s3d)));
            }
        }
        __syncthreads();

        // Reduction: 12 items (pair, si, o) x 8 lanes = 96 threads (3 FULL
        // warps, every slot valid). Each lane sums 16 F2 (stride 8 points),
        // then 3-stage shfl within the 8-lane group; lane0 writes 2 floats.
        if (tid < 96) {
            const int item = tid >> 3;        // 0..11
            const int l8   = tid & 7;
            const int pair = item / (T * 3);
            const int rem  = item - (T * 3) * pair;
            const int si   = rem / 3;
            const int o    = rem - 3 * si;
            const F2* prp = part + (pair * T + si) * ROWF + o + 3 * l8;
            F2 a0 = 0, a1 = 0, a2 = 0, a3 = 0;
#pragma unroll
            for (int j = 0; j < 16; j += 4) {
                a0 = add2(a0, prp[24 * j]);
                a1 = add2(a1, prp[24 * (j + 1)]);
                a2 = add2(a2, prp[24 * (j + 2)]);
                a3 = add2(a3, prp[24 * (j + 3)]);
            }
            const F2 t = add2(add2(a0, a1), add2(a2, a3));
            float lo, hi;
            upk2(t, lo, hi);
            lo += __shfl_xor_sync(0xffffffffu, lo, 1);
            hi += __shfl_xor_sync(0xffffffffu, hi, 1);
            lo += __shfl_xor_sync(0xffffffffu, lo, 2);
            hi += __shfl_xor_sync(0xffffffffu, hi, 2);
            lo += __shfl_xor_sync(0xffffffffu, lo, 4);
            hi += __shfl_xor_sync(0xffffffffu, hi, 4);
            if ((tid & 7) == 0) {
                const int idx = (s0i + si) * 3 + o;
                ob[(long)(2 * pair) * (Ss * 3) + idx]     = lo;
                ob[(long)(2 * pair + 1) * (Ss * 3) + idx] = hi;
            }
        }
        __syncthreads();
    }
}

extern "C" void kernel_launch(void* const* d_in, const int* in_sizes, int n_in,
                              void* d_out, int out_size) {
    const float* x  = (const float*)d_in[0];
    const float* W1 = (const float*)d_in[1];
    const float* W2 = (const float*)d_in[2];
    prnn_kernel<<<Bb / 4, TPB>>>(x, W1, W2, (float*)d_out);
}